// round 3
// baseline (speedup 1.0000x reference)
#include <cuda_runtime.h>

// LIF feed-forward scan, float2-vectorized.
// x: [T, B, N] f32 viewed as [T, BN/2] float2. Each thread owns 2 adjacent
// (b,n) columns; serial recurrence over t.
// Middle ground between R1 (scalar, 8192 warps, LSU-heavy) and R2 (float4,
// 2048 warps, concurrency-starved): 4096 warps (~28/SM) with half of R1's
// memory-instruction count. Default cache policy (the .cs hints of R2 were
// confounded with the regression; reverting).
//
// v' = v + 0.1*((0 - v) + i) ; i' = 0.8*i ; z = (v' > 1) ; v = (1-z)*v' ; i = i' + x

__global__ void __launch_bounds__(128) lif_scan_v2_kernel(
    const float2* __restrict__ x,
    float2* __restrict__ out,
    int cols,   // BN/2
    int T)
{
    int idx = blockIdx.x * blockDim.x + threadIdx.x;
    if (idx >= cols) return;

    const float kMem = 0.1f;   // DT * TAU_MEM_INV
    const float kSyn = 0.8f;   // 1 - DT * TAU_SYN_INV
    const float vth  = 1.0f;

    float v0 = 0.f, v1 = 0.f;
    float i0 = 0.f, i1 = 0.f;

    const float2* xp = x + idx;
    float2* op = out + idx;
    long long stride = (long long)cols;

    for (int t = 0; t < T; t += 8) {
        // Front-batch 8 independent 64-bit loads (x is state-independent):
        // MLP = 8 per thread.
        float2 xr[8];
        #pragma unroll
        for (int u = 0; u < 8; ++u)
            xr[u] = xp[(long long)(t + u) * stride];

        #pragma unroll
        for (int u = 0; u < 8; ++u) {
            float2 zout;

            float vd0 = v0 + kMem * ((0.0f - v0) + i0);
            zout.x = (vd0 - vth > 0.0f) ? 1.0f : 0.0f;
            v0 = (zout.x == 0.0f) ? vd0 : 0.0f;
            i0 = i0 * kSyn + xr[u].x;

            float vd1 = v1 + kMem * ((0.0f - v1) + i1);
            zout.y = (vd1 - vth > 0.0f) ? 1.0f : 0.0f;
            v1 = (zout.y == 0.0f) ? vd1 : 0.0f;
            i1 = i1 * kSyn + xr[u].y;

            op[(long long)(t + u) * stride] = zout;
        }
    }
}

extern "C" void kernel_launch(void* const* d_in, const int* in_sizes, int n_in,
                              void* d_out, int out_size) {
    const float2* x = (const float2*)d_in[0];
    float2* out = (float2*)d_out;

    const int T = 256;
    const int BN = in_sizes[0] / T;   // 262144
    const int cols = BN / 2;          // 131072

    int threads = 128;
    int blocks = (cols + threads - 1) / threads;  // 1024
    lif_scan_v2_kernel<<<blocks, threads>>>(x, out, cols, T);
}

// round 4
// speedup vs baseline: 1.0116x; 1.0116x over previous
#include <cuda_runtime.h>

// LIF feed-forward scan, float2-vectorized, streaming stores.
// x: [T, B, N] f32 viewed as [T, BN/2] float2. Each thread owns 2 adjacent
// (b,n) columns; serial recurrence over t.
//
// Loads: default policy (normal L2 allocation).
// Stores: st.global.cs — spikes are written once and never re-read; evict-first
// keeps L2 clean of dirty output lines between graph replays (harness times
// back-to-back replays; dirty-writeback contention showed up as the
// ncu-vs-bench gap in R3).
//
// v' = v + 0.1*((0 - v) + i) ; i' = 0.8*i ; z = (v' > 1) ; v = (1-z)*v' ; i = i' + x

__device__ __forceinline__ void stcs2(float2* p, float2 v) {
    asm volatile("st.global.cs.v2.f32 [%0], {%1,%2};"
                 :: "l"(p), "f"(v.x), "f"(v.y) : "memory");
}

__global__ void __launch_bounds__(128) lif_scan_v2cs_kernel(
    const float2* __restrict__ x,
    float2* __restrict__ out,
    int cols,   // BN/2
    int T)
{
    int idx = blockIdx.x * blockDim.x + threadIdx.x;
    if (idx >= cols) return;

    const float kMem = 0.1f;   // DT * TAU_MEM_INV
    const float kSyn = 0.8f;   // 1 - DT * TAU_SYN_INV
    const float vth  = 1.0f;

    float v0 = 0.f, v1 = 0.f;
    float i0 = 0.f, i1 = 0.f;

    const float2* xp = x + idx;
    float2* op = out + idx;
    long long stride = (long long)cols;

    for (int t = 0; t < T; t += 8) {
        // Front-batch 8 independent 64-bit loads (x is state-independent):
        // MLP = 8 per thread.
        float2 xr[8];
        #pragma unroll
        for (int u = 0; u < 8; ++u)
            xr[u] = xp[(long long)(t + u) * stride];

        #pragma unroll
        for (int u = 0; u < 8; ++u) {
            float2 zout;

            float vd0 = v0 + kMem * ((0.0f - v0) + i0);
            zout.x = (vd0 - vth > 0.0f) ? 1.0f : 0.0f;
            v0 = (zout.x == 0.0f) ? vd0 : 0.0f;
            i0 = i0 * kSyn + xr[u].x;

            float vd1 = v1 + kMem * ((0.0f - v1) + i1);
            zout.y = (vd1 - vth > 0.0f) ? 1.0f : 0.0f;
            v1 = (zout.y == 0.0f) ? vd1 : 0.0f;
            i1 = i1 * kSyn + xr[u].y;

            stcs2(op + (long long)(t + u) * stride, zout);
        }
    }
}

extern "C" void kernel_launch(void* const* d_in, const int* in_sizes, int n_in,
                              void* d_out, int out_size) {
    const float2* x = (const float2*)d_in[0];
    float2* out = (float2*)d_out;

    const int T = 256;
    const int BN = in_sizes[0] / T;   // 262144
    const int cols = BN / 2;          // 131072

    int threads = 128;
    int blocks = (cols + threads - 1) / threads;  // 1024
    lif_scan_v2cs_kernel<<<blocks, threads>>>(x, out, cols, T);
}